// round 9
// baseline (speedup 1.0000x reference)
#include <cuda_runtime.h>

// ---------------------------------------------------------------------------
// SSIM loss, fully fused:  out = 1 - mean(ssim_map(img1, img2))
// (32,3,512,512) fp32, 11x11 Gaussian sigma=1.5, SAME zero padding.
//
// Blur 4 maps staged as interleaved float2 pairs: arrA=(x,y), arrB=(xx+yy,xy).
// One LDS.64 delivers an aligned map-pair; one fma.rn.f32x2 (weight (w,w))
// blurs both maps per issue slot -> horizontal AND vertical blur at half the
// issue slots, with zero pack instructions. 11-tap chains split 6+5 across
// two accumulators for ILP. Warp-autonomous 64-col strips, double-buffered
// warp-private smem (1 __syncwarp/row), register ring of 11 h-blurred rows
// (u64-packed), statically rotated ring indices (row_step<JJ>, compact
// round-6 loop skeleton). Branch-free borders. Fused deterministic final
// reduction via last-block atomic counter (self-resetting for graph replay).
// ---------------------------------------------------------------------------

namespace {
constexpr int HW      = 512;
constexpr int NT      = 128;                 // 4 warps per CTA
constexpr int RC      = 256;                 // output rows per CTA
constexpr int P2      = 76;                  // float2 slots per array (>=74)
constexpr int NCTAS   = 2 * 2 * 96;          // strips x chunks x planes = 384
constexpr int NPART   = NCTAS * 4;           // one partial per warp = 1536
constexpr float C1    = 0.01f * 0.01f;
constexpr float C2    = 0.03f * 0.03f;

// Normalized 1D Gaussian, window 11, sigma 1.5 (symmetric)
__device__ constexpr float WG[11] = {
    0.00102838f, 0.00759876f, 0.03600078f, 0.10936069f, 0.21300554f,
    0.26601173f,
    0.21300554f, 0.10936069f, 0.03600078f, 0.00759876f, 0.00102838f
};
}  // namespace

__device__ float g_partials[NPART];
__device__ int   g_count = 0;

typedef unsigned long long u64;

// Packed fp32x2 ops (sm_103a; not emitted by ptxas from plain C++)
#define FMA2(acc, val, w) \
    asm("fma.rn.f32x2 %0, %1, %2, %0;" : "+l"(acc) : "l"(val), "l"(w))
#define ADD2(d, a, b) \
    asm("add.rn.f32x2 %0, %1, %2;" : "=l"(d) : "l"(a), "l"(b))
#define UNPK(lo, hi, p) \
    asm("mov.b64 {%0, %1}, %2;" : "=f"(lo), "=f"(hi) : "l"(p))

// One row of the pipeline. JJ = i mod 11 (compile-time ring phase).
template <int JJ>
__device__ __forceinline__ void row_step(
    int i, int lane,
    const char* __restrict__ pc1, const char* __restrict__ pc2,
    int gy0,
    int off0, int off1, int off2,
    float cm0, float cm1, float cm2,
    float2* __restrict__ sw,
    u64 (&ring)[11][4],
    const u64 (&wpk)[6],
    float (&pa)[6], float& arm,
    float& lsum)
{
    // ---- prefetch raw row (gy0-4+i) into pb (hides DRAM latency) ----
    float pb[6];
    float brm;
    {
        int rr = gy0 - 4 + i;
        int rc = rr < 0 ? 0 : (rr > 511 ? 511 : rr);
        brm = (rr == rc) ? 1.f : 0.f;
        const char* r1 = pc1 + rc * 2048;
        const char* r2 = pc2 + rc * 2048;
        pb[0] = *(const float*)(r1 + off0);
        pb[1] = *(const float*)(r2 + off0);
        pb[2] = *(const float*)(r1 + off1);
        pb[3] = *(const float*)(r2 + off1);
        if (lane < 10) {
            pb[4] = *(const float*)(r1 + off2);
            pb[5] = *(const float*)(r2 + off2);
        } else {
            pb[4] = 0.f; pb[5] = 0.f;
        }
    }

    // ---- stage row i (in pa) as packed pairs: A=(x,y), B=(xx+yy, xy) ----
    float2* sbuf = sw + (i & 1) * (2 * P2);   // [arrA | arrB] per buffer
    {
        float m0 = cm0 * arm, m1 = cm1 * arm, m2 = cm2 * arm;
        float xm = pa[0] * m0, ym = pa[1] * m0;
        sbuf[lane]      = make_float2(xm, ym);
        sbuf[P2 + lane] = make_float2(fmaf(xm, xm, ym * ym), xm * ym);
        xm = pa[2] * m1; ym = pa[3] * m1;
        sbuf[lane + 32]      = make_float2(xm, ym);
        sbuf[P2 + lane + 32] = make_float2(fmaf(xm, xm, ym * ym), xm * ym);
        if (lane < 10) {
            xm = pa[4] * m2; ym = pa[5] * m2;
            sbuf[lane + 64]      = make_float2(xm, ym);
            sbuf[P2 + lane + 64] = make_float2(fmaf(xm, xm, ym * ym), xm * ym);
        }
    }
    __syncwarp();

    // ---- horizontal 11-tap blur, packed map-pairs (FFMA2) -> ring[JJ] ----
    // cols (2*lane, 2*lane+1) need staged positions 2*lane .. 2*lane+11
    {
        const u64* ldA = (const u64*)(sbuf) + 2 * lane;
        const u64* ldB = (const u64*)(sbuf + P2) + 2 * lane;
        u64 PV[12];
#pragma unroll
        for (int k = 0; k < 12; ++k) PV[k] = ldA[k];
        u64 a0p = 0ull, a0q = 0ull, a1p = 0ull, a1q = 0ull;
#pragma unroll
        for (int k = 0; k < 6; ++k) {
            FMA2(a0p, PV[k],     wpk[k <= 5 ? k : 10 - k]);
            FMA2(a1p, PV[k + 1], wpk[k <= 5 ? k : 10 - k]);
        }
#pragma unroll
        for (int k = 6; k < 11; ++k) {
            FMA2(a0q, PV[k],     wpk[10 - k]);
            FMA2(a1q, PV[k + 1], wpk[10 - k]);
        }
        ADD2(ring[JJ][0], a0p, a0q);
        ADD2(ring[JJ][1], a1p, a1q);
#pragma unroll
        for (int k = 0; k < 12; ++k) PV[k] = ldB[k];
        u64 b0p = 0ull, b0q = 0ull, b1p = 0ull, b1q = 0ull;
#pragma unroll
        for (int k = 0; k < 6; ++k) {
            FMA2(b0p, PV[k],     wpk[k]);
            FMA2(b1p, PV[k + 1], wpk[k]);
        }
#pragma unroll
        for (int k = 6; k < 11; ++k) {
            FMA2(b0q, PV[k],     wpk[10 - k]);
            FMA2(b1q, PV[k + 1], wpk[10 - k]);
        }
        ADD2(ring[JJ][2], b0p, b0q);
        ADD2(ring[JJ][3], b1p, b1q);
    }

    // ---- vertical 11-tap blur (FFMA2, split 6+5) + SSIM + accumulate ----
    if (i >= 10) {
        u64 vp[4] = {0ull, 0ull, 0ull, 0ull};
        u64 vq[4] = {0ull, 0ull, 0ull, 0ull};
#pragma unroll
        for (int m = 0; m < 11; ++m) {
            const int widx = 10 - ((JJ - m + 11) % 11);      // compile-time
            const int wi   = widx <= 5 ? widx : 10 - widx;   // symmetric
            if (m < 6) {
#pragma unroll
                for (int q = 0; q < 4; ++q) FMA2(vp[q], ring[m][q], wpk[wi]);
            } else {
#pragma unroll
                for (int q = 0; q < 4; ++q) FMA2(vq[q], ring[m][q], wpk[wi]);
            }
        }
        u64 vacc[4];
#pragma unroll
        for (int q = 0; q < 4; ++q) ADD2(vacc[q], vp[q], vq[q]);

        {   // column 0:  vacc[0]=(mu1,mu2)  vacc[2]=(bss,bxy)
            float mu1, mu2, bss, bxy;
            UNPK(mu1, mu2, vacc[0]);
            UNPK(bss, bxy, vacc[2]);
            float m12 = mu1 * mu2;
            float msq = fmaf(mu1, mu1, mu2 * mu2);
            float num = fmaf(2.f, m12, C1) * fmaf(2.f, bxy - m12, C2);
            float den = (msq + C1) * (bss - msq + C2);
            lsum += __fdividef(num, den);
        }
        {   // column 1
            float mu1, mu2, bss, bxy;
            UNPK(mu1, mu2, vacc[1]);
            UNPK(bss, bxy, vacc[3]);
            float m12 = mu1 * mu2;
            float msq = fmaf(mu1, mu1, mu2 * mu2);
            float num = fmaf(2.f, m12, C1) * fmaf(2.f, bxy - m12, C2);
            float den = (msq + C1) * (bss - msq + C2);
            lsum += __fdividef(num, den);
        }
    }

    // ---- rotate prefetch ----
#pragma unroll
    for (int k = 0; k < 6; ++k) pa[k] = pb[k];
    arm = brm;
}

__global__ void __launch_bounds__(NT, 3)
ssim_kernel(const float* __restrict__ img1, const float* __restrict__ img2,
            float* __restrict__ out)
{
    // per-warp staging: 2 buffers x [arrA(76) | arrB(76)] float2
    __shared__ __align__(16) float2 sb[4][2 * 2 * P2];
    __shared__ double sdbl[NT];
    __shared__ int    s_last;

    const int t     = threadIdx.x;
    const int w     = t >> 5;
    const int lane  = t & 31;
    const int strip = blockIdx.x;   // 0..1
    const int chunk = blockIdx.y;   // 0..1
    const int plane = blockIdx.z;   // 0..95

    const int gy0  = chunk * RC;
    const int col0 = strip * 256 + w * 64 - 5;  // global col of staging pos 0

    const char* pc1 = (const char*)(img1 + (size_t)plane * HW * HW);
    const char* pc2 = (const char*)(img2 + (size_t)plane * HW * HW);

    // Per-slot clamped byte offsets + validity masks (computed once)
    int   off0, off1, off2;
    float cm0, cm1, cm2;
    {
        int c;
        c = col0 + lane;
        cm0  = (c >= 0 && c < 512) ? 1.f : 0.f;
        off0 = (c < 0 ? 0 : (c > 511 ? 511 : c)) * 4;
        c = col0 + lane + 32;
        cm1  = (c >= 0 && c < 512) ? 1.f : 0.f;
        off1 = (c < 0 ? 0 : (c > 511 ? 511 : c)) * 4;
        c = col0 + lane + 64;
        cm2  = (c >= 0 && c < 512) ? 1.f : 0.f;
        off2 = (c < 0 ? 0 : (c > 511 ? 511 : c)) * 4;
    }

    // Packed (w, w) weights for FFMA2 (6 unique, symmetric window)
    u64 wpk[6];
#pragma unroll
    for (int k = 0; k < 6; ++k)
        asm("mov.b64 %0, {%1, %1};" : "=l"(wpk[k]) : "f"(WG[k]));

    float2* sw_ = &sb[w][0];
    u64 ring[11][4];
    float pa[6];
    float arm;
    float lsum = 0.f;

    // Initial prefetch: raw row gy0-5 (i = 0)
    {
        int rr = gy0 - 5;
        int rc = rr < 0 ? 0 : rr;  // never > 511 here
        arm = (rr == rc) ? 1.f : 0.f;
        const char* r1 = pc1 + rc * 2048;
        const char* r2 = pc2 + rc * 2048;
        pa[0] = *(const float*)(r1 + off0);
        pa[1] = *(const float*)(r2 + off0);
        pa[2] = *(const float*)(r1 + off1);
        pa[3] = *(const float*)(r2 + off1);
        if (lane < 10) {
            pa[4] = *(const float*)(r1 + off2);
            pa[5] = *(const float*)(r2 + off2);
        } else {
            pa[4] = 0.f; pa[5] = 0.f;
        }
    }

#define RS(I, J) row_step<J>((I), lane, pc1, pc2, gy0, off0, off1, off2, \
                             cm0, cm1, cm2, sw_, ring, wpk, pa, arm, lsum)

    // 266 iterations total = 24*11 + 2; outputs produced for i in [10, 266)
    for (int ib = 0; ib < 264; ib += 11) {
        RS(ib + 0, 0);  RS(ib + 1, 1);  RS(ib + 2, 2);  RS(ib + 3, 3);
        RS(ib + 4, 4);  RS(ib + 5, 5);  RS(ib + 6, 6);  RS(ib + 7, 7);
        RS(ib + 8, 8);  RS(ib + 9, 9);  RS(ib + 10, 10);
    }
    RS(264, 0);
    RS(265, 1);
#undef RS

    // ---- deterministic warp reduction -> per-warp global partial ----
#pragma unroll
    for (int o = 16; o > 0; o >>= 1)
        lsum += __shfl_down_sync(0xffffffffu, lsum, o);
    if (lane == 0)
        g_partials[(((plane * 2) + chunk) * 2 + strip) * 4 + w] = lsum;
    __syncthreads();

    // ---- last-block finalize (fused; deterministic; self-resetting) ----
    if (t == 0) {
        __threadfence();
        s_last = (atomicAdd(&g_count, 1) == NCTAS - 1) ? 1 : 0;
    }
    __syncthreads();
    if (s_last) {
        __threadfence();
        double acc = 0.0;
#pragma unroll
        for (int k = 0; k < NPART / NT; ++k)
            acc += (double)g_partials[t * (NPART / NT) + k];
        sdbl[t] = acc;
        __syncthreads();
        for (int o = 64; o > 0; o >>= 1) {
            if (t < o) sdbl[t] += sdbl[t + o];
            __syncthreads();
        }
        if (t == 0) {
            out[0] = (float)(1.0 - sdbl[0] / 25165824.0);  // 32*3*512*512
            g_count = 0;  // reset for next graph replay
        }
    }
}

extern "C" void kernel_launch(void* const* d_in, const int* in_sizes, int n_in,
                              void* d_out, int out_size) {
    (void)in_sizes; (void)n_in; (void)out_size;
    const float* img1 = (const float*)d_in[0];
    const float* img2 = (const float*)d_in[1];
    dim3 grid(2, 2, 96);  // strips x row-chunks x (N*C) planes
    ssim_kernel<<<grid, NT>>>(img1, img2, (float*)d_out);
}

// round 12
// speedup vs baseline: 1.0031x; 1.0031x over previous
#include <cuda_runtime.h>

// ---------------------------------------------------------------------------
// SSIM loss, fully fused:  out = 1 - mean(ssim_map(img1, img2))
// (32,3,512,512) fp32, 11x11 Gaussian sigma=1.5, SAME zero padding.
//
// Blur 4 maps {x, y, x*x+y*y, x*y} (SSIM only needs sigma1+sigma2).
// Warp-autonomous 64-col strips; per row: stage maps into warp-private
// double-buffered smem, prefetch next raw row directly into the staging
// registers (no rotation movs), 1 __syncwarp/row, 11-tap horizontal blur
// (all FFMA with immediate weights, rt=1), register ring of 11 h-blurred
// rows, 11-tap vertical blur with statically rotated ring indices
// (row_step<JJ>, compact 11-phase skeleton), SSIM epilogue with a single
// merged fast-division, accumulate. Branch-free borders: clamped
// incremented row pointers + {0,1} column masks folded into staging.
// Fused deterministic final reduction via last-block atomic counter
// (fixed-order double sum, self-resetting for graph replay).
// ---------------------------------------------------------------------------

namespace {
constexpr int HW      = 512;
constexpr int NT      = 128;                 // 4 warps per CTA
constexpr int RC      = 256;                 // output rows per CTA
constexpr int WSTRIDE = 80;                  // smem floats per map row (>=74)
constexpr int NCTAS   = 2 * 2 * 96;          // strips x chunks x planes = 384
constexpr int NPART   = NCTAS * 4;           // one partial per warp = 1536
constexpr float C1    = 0.01f * 0.01f;
constexpr float C2    = 0.03f * 0.03f;

// Normalized 1D Gaussian, window 11, sigma 1.5 (symmetric)
__device__ constexpr float WG[11] = {
    0.00102838f, 0.00759876f, 0.03600078f, 0.10936069f, 0.21300554f,
    0.26601173f,
    0.21300554f, 0.10936069f, 0.03600078f, 0.00759876f, 0.00102838f
};
}  // namespace

__device__ float g_partials[NPART];
__device__ int   g_count = 0;

// One row of the pipeline. JJ = i mod 11 (compile-time ring phase).
template <int JJ>
__device__ __forceinline__ void row_step(
    int i, int lane, int& rr,
    const char*& r1, const char*& r2,
    int off0, int off1, int off2,
    float cm0, float cm1, float cm2,
    float* __restrict__ sw,
    float (&ring)[11][4][2],
    float (&pa)[6], float& arm,
    float& lsum)
{
    // ---- stage row rr (held in pa): maps {x, y, x*x+y*y, x*y} ----
    float* sbuf = sw + (i & 1) * (4 * WSTRIDE);
    {
        float m0 = cm0 * arm, m1 = cm1 * arm, m2 = cm2 * arm;
        float xm = pa[0] * m0, ym = pa[1] * m0;
        int p = lane;
        sbuf[0 * WSTRIDE + p] = xm;
        sbuf[1 * WSTRIDE + p] = ym;
        sbuf[2 * WSTRIDE + p] = fmaf(xm, xm, ym * ym);
        sbuf[3 * WSTRIDE + p] = xm * ym;
        xm = pa[2] * m1; ym = pa[3] * m1; p = lane + 32;
        sbuf[0 * WSTRIDE + p] = xm;
        sbuf[1 * WSTRIDE + p] = ym;
        sbuf[2 * WSTRIDE + p] = fmaf(xm, xm, ym * ym);
        sbuf[3 * WSTRIDE + p] = xm * ym;
        if (lane < 10) {
            xm = pa[4] * m2; ym = pa[5] * m2; p = lane + 64;
            sbuf[0 * WSTRIDE + p] = xm;
            sbuf[1 * WSTRIDE + p] = ym;
            sbuf[2 * WSTRIDE + p] = fmaf(xm, xm, ym * ym);
            sbuf[3 * WSTRIDE + p] = xm * ym;
        }
    }

    // ---- prefetch next raw row (rr+1) back into pa (no rotation movs) ----
    {
        int nr = rr + 1;
        if ((unsigned)(nr - 1) < 511u) { r1 += 2048; r2 += 2048; }
        arm = ((unsigned)nr < 512u) ? 1.f : 0.f;
        rr = nr;
        pa[0] = *(const float*)(r1 + off0);
        pa[1] = *(const float*)(r2 + off0);
        pa[2] = *(const float*)(r1 + off1);
        pa[3] = *(const float*)(r2 + off1);
        if (lane < 10) {
            pa[4] = *(const float*)(r1 + off2);
            pa[5] = *(const float*)(r2 + off2);
        }
    }
    __syncwarp();

    // ---- horizontal 11-tap blur (FFMA-imm, rt=1) -> ring slot JJ ----
#pragma unroll
    for (int m = 0; m < 4; ++m) {
        const float* rp = sbuf + m * WSTRIDE + 2 * lane;
        float v[12];
#pragma unroll
        for (int k = 0; k < 6; ++k) {
            float2 q = *(const float2*)(rp + 2 * k);  // 8B aligned
            v[2 * k]     = q.x;
            v[2 * k + 1] = q.y;
        }
        float A = 0.f, B = 0.f;
#pragma unroll
        for (int k = 0; k < 11; ++k) {
            A = fmaf(WG[k], v[k],     A);
            B = fmaf(WG[k], v[k + 1], B);
        }
        ring[JJ][m][0] = A;
        ring[JJ][m][1] = B;
    }

    // ---- vertical 11-tap blur from registers + SSIM + accumulate ----
    if (i >= 10) {
        float s0[4] = {0.f, 0.f, 0.f, 0.f};
        float s1[4] = {0.f, 0.f, 0.f, 0.f};
#pragma unroll
        for (int m = 0; m < 11; ++m) {
            const float w = WG[10 - ((JJ - m + 11) % 11)];  // compile-time
#pragma unroll
            for (int q = 0; q < 4; ++q) {
                s0[q] = fmaf(w, ring[m][q][0], s0[q]);
                s1[q] = fmaf(w, ring[m][q][1], s1[q]);
            }
        }
        float n0, d0, n1, d1;
        {
            float mu1 = s0[0], mu2 = s0[1], bss = s0[2], bxy = s0[3];
            float m12 = mu1 * mu2;
            float msq = fmaf(mu1, mu1, mu2 * mu2);
            n0 = fmaf(2.f, m12, C1) * fmaf(2.f, bxy - m12, C2);
            d0 = (msq + C1) * (bss - msq + C2);
        }
        {
            float mu1 = s1[0], mu2 = s1[1], bss = s1[2], bxy = s1[3];
            float m12 = mu1 * mu2;
            float msq = fmaf(mu1, mu1, mu2 * mu2);
            n1 = fmaf(2.f, m12, C1) * fmaf(2.f, bxy - m12, C2);
            d1 = (msq + C1) * (bss - msq + C2);
        }
        // n0/d0 + n1/d1 with a single fast division (one MUFU.RCP)
        lsum += __fdividef(fmaf(n0, d1, n1 * d0), d0 * d1);
    }
}

__global__ void __launch_bounds__(NT, 3)
ssim_kernel(const float* __restrict__ img1, const float* __restrict__ img2,
            float* __restrict__ out)
{
    __shared__ __align__(16) float sb[4][2 * 4 * WSTRIDE];  // per-warp staging
    __shared__ double sdbl[NT];
    __shared__ int    s_last;

    const int t     = threadIdx.x;
    const int w     = t >> 5;
    const int lane  = t & 31;
    const int strip = blockIdx.x;   // 0..1
    const int chunk = blockIdx.y;   // 0..1
    const int plane = blockIdx.z;   // 0..95

    const int gy0  = chunk * RC;
    const int col0 = strip * 256 + w * 64 - 5;  // global col of staging pos 0

    // Per-slot clamped byte offsets + validity masks (computed once)
    int   off0, off1, off2;
    float cm0, cm1, cm2;
    {
        int c;
        c = col0 + lane;
        cm0  = (c >= 0 && c < 512) ? 1.f : 0.f;
        off0 = (c < 0 ? 0 : (c > 511 ? 511 : c)) * 4;
        c = col0 + lane + 32;
        cm1  = (c >= 0 && c < 512) ? 1.f : 0.f;
        off1 = (c < 0 ? 0 : (c > 511 ? 511 : c)) * 4;
        c = col0 + lane + 64;
        cm2  = (c >= 0 && c < 512) ? 1.f : 0.f;
        off2 = (c < 0 ? 0 : (c > 511 ? 511 : c)) * 4;
    }

    float* sw_ = &sb[w][0];
    float ring[11][4][2];
    float pa[6];
    float arm;
    float lsum = 0.f;

    // Initial prefetch: raw row gy0-5 into pa; row pointers track clamp(rr)
    int rr = gy0 - 5;
    const char* r1;
    const char* r2;
    {
        int rcl = rr < 0 ? 0 : rr;  // never > 511 here
        arm = (rr == rcl) ? 1.f : 0.f;
        r1 = (const char*)(img1 + (size_t)plane * HW * HW) + rcl * 2048;
        r2 = (const char*)(img2 + (size_t)plane * HW * HW) + rcl * 2048;
        pa[0] = *(const float*)(r1 + off0);
        pa[1] = *(const float*)(r2 + off0);
        pa[2] = *(const float*)(r1 + off1);
        pa[3] = *(const float*)(r2 + off1);
        if (lane < 10) {
            pa[4] = *(const float*)(r1 + off2);
            pa[5] = *(const float*)(r2 + off2);
        } else {
            pa[4] = 0.f; pa[5] = 0.f;
        }
    }

#define RS(I, J) row_step<J>((I), lane, rr, r1, r2, off0, off1, off2, \
                             cm0, cm1, cm2, sw_, ring, pa, arm, lsum)

    // 266 iterations total = 24*11 + 2; outputs produced for i in [10, 266)
    for (int ib = 0; ib < 264; ib += 11) {
        RS(ib + 0, 0);  RS(ib + 1, 1);  RS(ib + 2, 2);  RS(ib + 3, 3);
        RS(ib + 4, 4);  RS(ib + 5, 5);  RS(ib + 6, 6);  RS(ib + 7, 7);
        RS(ib + 8, 8);  RS(ib + 9, 9);  RS(ib + 10, 10);
    }
    RS(264, 0);
    RS(265, 1);
#undef RS

    // ---- deterministic warp reduction -> per-warp global partial ----
#pragma unroll
    for (int o = 16; o > 0; o >>= 1)
        lsum += __shfl_down_sync(0xffffffffu, lsum, o);
    if (lane == 0)
        g_partials[(((plane * 2) + chunk) * 2 + strip) * 4 + w] = lsum;
    __syncthreads();

    // ---- last-block finalize (fused; deterministic; self-resetting) ----
    if (t == 0) {
        __threadfence();
        s_last = (atomicAdd(&g_count, 1) == NCTAS - 1) ? 1 : 0;
    }
    __syncthreads();
    if (s_last) {
        __threadfence();
        double acc = 0.0;
#pragma unroll
        for (int k = 0; k < NPART / NT; ++k)
            acc += (double)g_partials[t * (NPART / NT) + k];
        sdbl[t] = acc;
        __syncthreads();
        for (int o = 64; o > 0; o >>= 1) {
            if (t < o) sdbl[t] += sdbl[t + o];
            __syncthreads();
        }
        if (t == 0) {
            out[0] = (float)(1.0 - sdbl[0] / 25165824.0);  // 32*3*512*512
            g_count = 0;  // reset for next graph replay
        }
    }
}

extern "C" void kernel_launch(void* const* d_in, const int* in_sizes, int n_in,
                              void* d_out, int out_size) {
    (void)in_sizes; (void)n_in; (void)out_size;
    const float* img1 = (const float*)d_in[0];
    const float* img2 = (const float*)d_in[1];
    dim3 grid(2, 2, 96);  // strips x row-chunks x (N*C) planes
    ssim_kernel<<<grid, NT>>>(img1, img2, (float*)d_out);
}